// round 16
// baseline (speedup 1.0000x reference)
#include <cuda_runtime.h>
#include <cstdint>

// StochasticPool2d: x (16,96,224,224) f32, 2x2 non-overlapping windows.
// Reference: jax.random.categorical(key(42), window_vals) == Gumbel-max with
// threefry-2x32 (partitionable counter mode); output = sampled window value.
//
// B=16 C=96 H=224 W=224 -> OH=OW=112
// R15 = R14 (4 windows/thread, float4 store, base-2 fast scoring + certified
// margin + bit-exact fallback) with the second window-pair's loads DEFERRED
// until after the first pair is computed: lower peak register pressure
// (regs ~40 -> ~33, occ 62% -> ~78%) and no front-batched MLP-4 load burst.
// Thread (tx,ty) in block (28,8), grid (14,1536):
//   oh = bx*8+ty, rowid = by*112+oh, quad q = tx (ow = 4q..4q+3)
//   in_base = rowid*448 + 8q ; cbase = rowid*448 + 16q ; out = rowid*112 + 4q

static constexpr uint32_t TF_K1 = 42u;
static constexpr uint32_t TF_K2 = 0x1BD11BDAu ^ 0u ^ 42u;  // ks[2]

__device__ __forceinline__ uint32_t rotl32(uint32_t x, int d) {
    return __funnelshift_l(x, x, d);
}

// threefry2x32, key=(0,42), counter=(0, n); returns out0 ^ out1.
__device__ __forceinline__ uint32_t threefry_bits(uint32_t n) {
    uint32_t x0 = 0u;        // counter_hi + ks[0] (both 0)
    uint32_t x1 = n + TF_K1; // counter_lo + ks[1]
#define TF_ROUND(r) { x0 += x1; x1 = rotl32(x1, (r)) ^ x0; }
    TF_ROUND(13) TF_ROUND(15) TF_ROUND(26) TF_ROUND(6)
    x0 += TF_K1;        x1 += TF_K2 + 1u;
    TF_ROUND(17) TF_ROUND(29) TF_ROUND(16) TF_ROUND(24)
    x0 += TF_K2;        x1 += 0u + 2u;
    TF_ROUND(13) TF_ROUND(15) TF_ROUND(26) TF_ROUND(6)
    /* ks[0]=0 */       x1 += TF_K1 + 3u;
    TF_ROUND(17) TF_ROUND(29) TF_ROUND(16) TF_ROUND(24)
    x0 += TF_K1;        x1 += TF_K2 + 4u;
    TF_ROUND(13) TF_ROUND(15) TF_ROUND(26) TF_ROUND(6)
    x0 += TF_K2;        x1 += 0u + 5u;
#undef TF_ROUND
    return x0 ^ x1;
}

// bits -> uniform(tiny,1), matching jax _uniform in f32 exactly.
__device__ __forceinline__ float uniform32(uint32_t bits) {
    float f = __uint_as_float((bits >> 9) | 0x3f800000u) - 1.0f;
    return fmaxf(f, 1.17549435e-38f);
}

// Exact gumbel (matches XLA f32: precise logf == __nv_logf).
__device__ __forceinline__ float gumbel_exact(float u) {
    return -logf(-logf(u));
}

__device__ __forceinline__ float rcp_approx(float x) {
    float r;
    asm("rcp.approx.f32 %0, %1;" : "=f"(r) : "f"(x));
    return r;
}

// One 2x2 window. Fast path in base 2:
//   L = -lg2(u) in (0, 127]; score (up to a shared additive constant):
//   s = v - ln2*__log2f(-__log2f(u)).
// MUFU.LG2 abs error ~4e-6 per log; d lg2(L) <= errL/(L ln2), so
// |s - s*| <= ~3e-5 + 4e-6/min_L. Certify when min_L >= 2e-3 and top1-top2
// margin > 8e-5 + 1e-5/min_L (>= 2x bound + rcp slop); else exact recompute.
__device__ __forceinline__ float pool_window(float v0, float v1, float v2, float v3,
                                             float u0, float u1, float u2, float u3) {
    const float NLN2 = -0.69314718055994531f;
    float l0 = __log2f(u0), l1 = __log2f(u1), l2 = __log2f(u2), l3 = __log2f(u3);
    float m0 = __log2f(-l0), m1 = __log2f(-l1), m2 = __log2f(-l2), m3 = __log2f(-l3);
    float s0 = fmaf(NLN2, m0, v0), s1 = fmaf(NLN2, m1, v1);
    float s2 = fmaf(NLN2, m2, v2), s3 = fmaf(NLN2, m3, v3);

    // first-max scan with second-max tracking
    float best = s0, second = -3.4e38f, val = v0;
    if (s1 > best) { second = best; best = s1; val = v1; } else second = s1;
    if (s2 > best) { second = best; best = s2; val = v2; }
    else if (s2 > second) second = s2;
    if (s3 > best) { second = best; best = s3; val = v3; }
    else if (s3 > second) second = s3;

    float minL = -fmaxf(fmaxf(l0, l1), fmaxf(l2, l3));  // min of -lg2(u)
    float E = fmaf(rcp_approx(minL), 1e-5f, 8e-5f);

    bool certain = (minL >= 2e-3f) && (best - second > E);
    if (!certain) {
        // Bit-exact reference path (rare, ~0.6%).
        float G0 = gumbel_exact(u0), G1 = gumbel_exact(u1);
        float G2 = gumbel_exact(u2), G3 = gumbel_exact(u3);
        float S0 = v0 + G0, S1 = v1 + G1, S2 = v2 + G2, S3 = v3 + G3;
        float B = S0; val = v0;
        if (S1 > B) { B = S1; val = v1; }
        if (S2 > B) { B = S2; val = v2; }
        if (S3 > B) { B = S3; val = v3; }
    }
    return val;
}

// Process one window-pair: loads its own two float4 rows, returns two outputs.
__device__ __forceinline__ float2 pool_pair(const float* __restrict__ x,
                                            uint32_t in_off, uint32_t cb) {
    float4 r0 = *reinterpret_cast<const float4*>(x + in_off);
    float4 r1 = *reinterpret_cast<const float4*>(x + in_off + 224u);
    float u[8];
#pragma unroll
    for (int k = 0; k < 8; k++)
        u[k] = uniform32(threefry_bits(cb + (uint32_t)k));
    float o0 = pool_window(r0.x, r0.y, r1.x, r1.y, u[0], u[1], u[2], u[3]);
    float o1 = pool_window(r0.z, r0.w, r1.z, r1.w, u[4], u[5], u[6], u[7]);
    return make_float2(o0, o1);
}

__global__ void __launch_bounds__(224)
stochpool_kernel(const float* __restrict__ x, float* __restrict__ out) {
    // block (28,8): tx = ow-quad, ty = oh sub-row; grid (14,1536): bx->oh, by->bc
    uint32_t tx    = threadIdx.x;                       // 0..27
    uint32_t oh    = blockIdx.x * 8u + threadIdx.y;     // 0..111
    uint32_t rowid = blockIdx.y * 112u + oh;            // bc*112 + oh

    uint32_t base448 = rowid * 448u;
    uint32_t in_base = base448 + 8u * tx;               // input cols 8q..8q+7
    uint32_t cbase   = base448 + 16u * tx;              // 16 counters per thread

    // First pair (cols 8q..8q+3), then second pair (cols 8q+4..8q+7) — loads
    // deferred to keep live registers low.
    float2 p0 = pool_pair(x, in_base,      cbase);
    float2 p1 = pool_pair(x, in_base + 4u, cbase + 8u);

    uint32_t out_base = rowid * 112u + 4u * tx;         // 16B aligned
    *reinterpret_cast<float4*>(out + out_base) =
        make_float4(p0.x, p0.y, p1.x, p1.y);
}

extern "C" void kernel_launch(void* const* d_in, const int* in_sizes, int n_in,
                              void* d_out, int out_size) {
    const float* x = (const float*)d_in[0];
    float* out = (float*)d_out;
    (void)in_sizes; (void)n_in; (void)out_size;
    dim3 block(28, 8, 1);
    dim3 grid(14, 1536, 1);
    stochpool_kernel<<<grid, block>>>(x, out);
}

// round 17
// speedup vs baseline: 1.0461x; 1.0461x over previous
#include <cuda_runtime.h>
#include <cstdint>

// StochasticPool2d: x (16,96,224,224) f32, 2x2 non-overlapping windows.
// Reference: jax.random.categorical(key(42), window_vals) == Gumbel-max with
// threefry-2x32 (partitionable counter mode); output = sampled window value.
//
// B=16 C=96 H=224 W=224 -> OH=OW=112
// FINAL (R14 structure, re-verified): 4 windows/thread, float4 store, 2-D
// launch (no div/mod prologue), base-2 fast gumbel scoring with certified
// margin + bit-exact precise-logf fallback. The kernel runs at ~109% of the
// hard alu-pipe floor set by 16 bit-exact threefry-2x32 calls per thread;
// pipe-rebalancing (R6/R7/R11) and occupancy (R15) were measured dead ends.
// Thread (tx,ty) in block (28,8), grid (14,1536):
//   oh = bx*8+ty, rowid = by*112+oh, quad q = tx (ow = 4q..4q+3)
//   in_base = rowid*448 + 8q ; cbase = rowid*448 + 16q ; out = rowid*112 + 4q

static constexpr uint32_t TF_K1 = 42u;
static constexpr uint32_t TF_K2 = 0x1BD11BDAu ^ 0u ^ 42u;  // ks[2]

__device__ __forceinline__ uint32_t rotl32(uint32_t x, int d) {
    return __funnelshift_l(x, x, d);
}

// threefry2x32, key=(0,42), counter=(0, n); returns out0 ^ out1.
__device__ __forceinline__ uint32_t threefry_bits(uint32_t n) {
    uint32_t x0 = 0u;        // counter_hi + ks[0] (both 0)
    uint32_t x1 = n + TF_K1; // counter_lo + ks[1]
#define TF_ROUND(r) { x0 += x1; x1 = rotl32(x1, (r)) ^ x0; }
    TF_ROUND(13) TF_ROUND(15) TF_ROUND(26) TF_ROUND(6)
    x0 += TF_K1;        x1 += TF_K2 + 1u;
    TF_ROUND(17) TF_ROUND(29) TF_ROUND(16) TF_ROUND(24)
    x0 += TF_K2;        x1 += 0u + 2u;
    TF_ROUND(13) TF_ROUND(15) TF_ROUND(26) TF_ROUND(6)
    /* ks[0]=0 */       x1 += TF_K1 + 3u;
    TF_ROUND(17) TF_ROUND(29) TF_ROUND(16) TF_ROUND(24)
    x0 += TF_K1;        x1 += TF_K2 + 4u;
    TF_ROUND(13) TF_ROUND(15) TF_ROUND(26) TF_ROUND(6)
    x0 += TF_K2;        x1 += 0u + 5u;
#undef TF_ROUND
    return x0 ^ x1;
}

// bits -> uniform(tiny,1), matching jax _uniform in f32 exactly.
__device__ __forceinline__ float uniform32(uint32_t bits) {
    float f = __uint_as_float((bits >> 9) | 0x3f800000u) - 1.0f;
    return fmaxf(f, 1.17549435e-38f);
}

// Exact gumbel (matches XLA f32: precise logf == __nv_logf).
__device__ __forceinline__ float gumbel_exact(float u) {
    return -logf(-logf(u));
}

__device__ __forceinline__ float rcp_approx(float x) {
    float r;
    asm("rcp.approx.f32 %0, %1;" : "=f"(r) : "f"(x));
    return r;
}

// One 2x2 window. Fast path in base 2:
//   L = -lg2(u) in (0, 127]; score (up to a shared additive constant):
//   s = v - ln2*__log2f(-__log2f(u)).
// MUFU.LG2 abs error ~4e-6 per log; d lg2(L) <= errL/(L ln2), so
// |s - s*| <= ~3e-5 + 4e-6/min_L. Certify when min_L >= 2e-3 and top1-top2
// margin > 8e-5 + 1e-5/min_L (>= 2x bound + rcp slop); else exact recompute.
__device__ __forceinline__ float pool_window(float v0, float v1, float v2, float v3,
                                             float u0, float u1, float u2, float u3) {
    const float NLN2 = -0.69314718055994531f;
    float l0 = __log2f(u0), l1 = __log2f(u1), l2 = __log2f(u2), l3 = __log2f(u3);
    float m0 = __log2f(-l0), m1 = __log2f(-l1), m2 = __log2f(-l2), m3 = __log2f(-l3);
    float s0 = fmaf(NLN2, m0, v0), s1 = fmaf(NLN2, m1, v1);
    float s2 = fmaf(NLN2, m2, v2), s3 = fmaf(NLN2, m3, v3);

    // first-max scan with second-max tracking
    float best = s0, second = -3.4e38f, val = v0;
    if (s1 > best) { second = best; best = s1; val = v1; } else second = s1;
    if (s2 > best) { second = best; best = s2; val = v2; }
    else if (s2 > second) second = s2;
    if (s3 > best) { second = best; best = s3; val = v3; }
    else if (s3 > second) second = s3;

    float minL = -fmaxf(fmaxf(l0, l1), fmaxf(l2, l3));  // min of -lg2(u)
    float E = fmaf(rcp_approx(minL), 1e-5f, 8e-5f);

    bool certain = (minL >= 2e-3f) && (best - second > E);
    if (!certain) {
        // Bit-exact reference path (rare, ~0.6%).
        float G0 = gumbel_exact(u0), G1 = gumbel_exact(u1);
        float G2 = gumbel_exact(u2), G3 = gumbel_exact(u3);
        float S0 = v0 + G0, S1 = v1 + G1, S2 = v2 + G2, S3 = v3 + G3;
        float B = S0; val = v0;
        if (S1 > B) { B = S1; val = v1; }
        if (S2 > B) { B = S2; val = v2; }
        if (S3 > B) { B = S3; val = v3; }
    }
    return val;
}

__global__ void __launch_bounds__(224)
stochpool_kernel(const float* __restrict__ x, float* __restrict__ out) {
    // block (28,8): tx = ow-quad, ty = oh sub-row; grid (14,1536): bx->oh, by->bc
    uint32_t tx    = threadIdx.x;                       // 0..27
    uint32_t oh    = blockIdx.x * 8u + threadIdx.y;     // 0..111
    uint32_t rowid = blockIdx.y * 112u + oh;            // bc*112 + oh

    uint32_t base448 = rowid * 448u;
    uint32_t in_base = base448 + 8u * tx;               // input cols 8q..8q+7
    uint32_t cbase   = base448 + 16u * tx;              // 16 counters per thread

    // windows 0,1: cols 8q..8q+3 ; windows 2,3: cols 8q+4..8q+7
    float4 a0 = *reinterpret_cast<const float4*>(x + in_base);
    float4 a1 = *reinterpret_cast<const float4*>(x + in_base + 224u);
    float4 b0 = *reinterpret_cast<const float4*>(x + in_base + 4u);
    float4 b1 = *reinterpret_cast<const float4*>(x + in_base + 228u);

    float u[8];
#pragma unroll
    for (int k = 0; k < 8; k++)
        u[k] = uniform32(threefry_bits(cbase + (uint32_t)k));
    float o0 = pool_window(a0.x, a0.y, a1.x, a1.y, u[0], u[1], u[2], u[3]);
    float o1 = pool_window(a0.z, a0.w, a1.z, a1.w, u[4], u[5], u[6], u[7]);

#pragma unroll
    for (int k = 0; k < 8; k++)
        u[k] = uniform32(threefry_bits(cbase + 8u + (uint32_t)k));
    float o2 = pool_window(b0.x, b0.y, b1.x, b1.y, u[0], u[1], u[2], u[3]);
    float o3 = pool_window(b0.z, b0.w, b1.z, b1.w, u[4], u[5], u[6], u[7]);

    uint32_t out_base = rowid * 112u + 4u * tx;         // 16B aligned
    *reinterpret_cast<float4*>(out + out_base) = make_float4(o0, o1, o2, o3);
}

extern "C" void kernel_launch(void* const* d_in, const int* in_sizes, int n_in,
                              void* d_out, int out_size) {
    const float* x = (const float*)d_in[0];
    float* out = (float*)d_out;
    (void)in_sizes; (void)n_in; (void)out_size;
    dim3 block(28, 8, 1);
    dim3 grid(14, 1536, 1);
    stochpool_kernel<<<grid, block>>>(x, out);
}